// round 1
// baseline (speedup 1.0000x reference)
#include <cuda_runtime.h>
#include <math.h>

// Problem constants (fixed shapes)
#define SEQ     4096
#define DMODEL  2048
#define DHEAD   128
#define NH      16
#define NKV     4
#define NCOLS   3072   // 16*128 (Q) + 4*128 (K) + 4*128 (V)

// ---------------- scratch (static __device__, no allocation) ----------------
__device__ float g_Wcat[DMODEL * NCOLS];   // repacked QKV weights [K=2048][N=3072]
__device__ float g_bcat[NCOLS];            // concatenated bias
__device__ float g_qkv[SEQ * NCOLS];       // projected q|k|v per row
__device__ float g_z[SEQ * DMODEL];        // attention output (pre O-proj)

// ---------------- weight repack + bias concat ----------------
__global__ void repack_kernel(const float* __restrict__ WQ, const float* __restrict__ WK,
                              const float* __restrict__ WV, const float* __restrict__ bQ,
                              const float* __restrict__ bK, const float* __restrict__ bV) {
    int idx = blockIdx.x * blockDim.x + threadIdx.x;
    if (idx < NCOLS) {
        float b;
        if      (idx < 2048) b = bQ[idx];
        else if (idx < 2560) b = bK[idx - 2048];
        else                 b = bV[idx - 2560];
        g_bcat[idx] = b;
    }
    if (idx >= DMODEL * NCOLS) return;
    int col = idx % NCOLS;
    int m   = idx / NCOLS;
    float v;
    if (col < 2048) {
        int n = col >> 7, h = col & 127;
        v = WQ[(n * DMODEL + m) * DHEAD + h];
    } else if (col < 2560) {
        int n = (col - 2048) >> 7, h = col & 127;
        v = WK[(n * DMODEL + m) * DHEAD + h];
    } else {
        int n = (col - 2560) >> 7, h = col & 127;
        v = WV[(n * DMODEL + m) * DHEAD + h];
    }
    g_Wcat[idx] = v;
}

// ---------------- SGEMM: C[M,N] = A[M,K] * B[K,N] + bias ----------------
#define BM 128
#define BN 128
#define BK 16

__global__ __launch_bounds__(256) void sgemm_bias(
    const float* __restrict__ A, const float* __restrict__ B,
    const float* __restrict__ bias, float* __restrict__ C,
    int M, int N, int K)
{
    __shared__ float As[BK][BM + 4];
    __shared__ float Bs[BK][BN + 4];
    int tid = threadIdx.x;
    int bm = blockIdx.y * BM;
    int bn = blockIdx.x * BN;

    int tm4 = (tid >> 4) * 4;   // thread row base (and +64)
    int tn4 = (tid & 15) * 4;   // thread col base (and +64)

    int arow = tid >> 1;          // A tile loader: 128 rows x 16 cols
    int acol = (tid & 1) * 8;
    int brow = tid >> 4;          // B tile loader: 16 rows x 128 cols
    int bcol = (tid & 15) * 8;

    const float* Aptr = A + (size_t)(bm + arow) * K + acol;
    const float* Bptr = B + (size_t)brow * N + bn + bcol;

    float acc[8][8];
    #pragma unroll
    for (int i = 0; i < 8; i++)
        #pragma unroll
        for (int j = 0; j < 8; j++) acc[i][j] = 0.f;

    for (int k0 = 0; k0 < K; k0 += BK) {
        float4 a0 = *(const float4*)(Aptr + k0);
        float4 a1 = *(const float4*)(Aptr + k0 + 4);
        float4 b0 = *(const float4*)(Bptr + (size_t)k0 * N);
        float4 b1 = *(const float4*)(Bptr + (size_t)k0 * N + 4);
        As[acol + 0][arow] = a0.x; As[acol + 1][arow] = a0.y;
        As[acol + 2][arow] = a0.z; As[acol + 3][arow] = a0.w;
        As[acol + 4][arow] = a1.x; As[acol + 5][arow] = a1.y;
        As[acol + 6][arow] = a1.z; As[acol + 7][arow] = a1.w;
        *(float4*)&Bs[brow][bcol]     = b0;
        *(float4*)&Bs[brow][bcol + 4] = b1;
        __syncthreads();
        #pragma unroll
        for (int kk = 0; kk < BK; kk++) {
            float4 af0 = *(const float4*)&As[kk][tm4];
            float4 af1 = *(const float4*)&As[kk][tm4 + 64];
            float4 bf0 = *(const float4*)&Bs[kk][tn4];
            float4 bf1 = *(const float4*)&Bs[kk][tn4 + 64];
            float a[8] = {af0.x, af0.y, af0.z, af0.w, af1.x, af1.y, af1.z, af1.w};
            float b[8] = {bf0.x, bf0.y, bf0.z, bf0.w, bf1.x, bf1.y, bf1.z, bf1.w};
            #pragma unroll
            for (int i = 0; i < 8; i++)
                #pragma unroll
                for (int j = 0; j < 8; j++)
                    acc[i][j] = fmaf(a[i], b[j], acc[i][j]);
        }
        __syncthreads();
    }

    float bv[8];
    #pragma unroll
    for (int j = 0; j < 8; j++) {
        int c = bn + (j < 4 ? tn4 + j : 64 + tn4 + j - 4);
        bv[j] = bias[c];
    }
    #pragma unroll
    for (int i = 0; i < 8; i++) {
        int r = bm + (i < 4 ? tm4 + i : 64 + tm4 + i - 4);
        float4 o0 = make_float4(acc[i][0] + bv[0], acc[i][1] + bv[1],
                                acc[i][2] + bv[2], acc[i][3] + bv[3]);
        float4 o1 = make_float4(acc[i][4] + bv[4], acc[i][5] + bv[5],
                                acc[i][6] + bv[6], acc[i][7] + bv[7]);
        *(float4*)&C[(size_t)r * N + bn + tn4]      = o0;
        *(float4*)&C[(size_t)r * N + bn + 64 + tn4] = o1;
    }
}

// ---------------- rotary (interleaved pairs, full head dim) ----------------
__global__ void rotary_kernel() {
    int idx = blockIdx.x * blockDim.x + threadIdx.x;
    const int total = SEQ * 20 * 64;   // 16 q heads + 4 k heads, 64 pairs each
    if (idx >= total) return;
    int j    = idx & 63;
    int rest = idx >> 6;
    int head = rest % 20;
    int s    = rest / 20;
    // freq in double then round to fp32 (matches jnp fp32 pow within ~1 ulp);
    // cos/sin in double of the fp32 angle: immune to fast-math range reduction.
    double dfreq = pow(10000.0, -(double)j / 64.0);
    float  freq  = (float)dfreq;
    float  angle = (float)s * freq;          // fp32 product, like jnp.outer
    double da = (double)angle;
    float c  = (float)cos(da);
    float sn = (float)sin(da);
    int off = (head < 16) ? head * 128 : 2048 + (head - 16) * 128;
    float* p = g_qkv + (size_t)s * NCOLS + off + 2 * j;
    float x1 = p[0], x2 = p[1];
    p[0] = x1 * c  - x2 * sn;
    p[1] = x1 * sn + x2 * c;
}

// ---------------- flash attention (causal, fp32) ----------------
#define BQ   64
#define BKV  64
#define QSTR 132          // 128 + 4 pad
#define PSTR 68           // 64 + 4 pad
#define ATTN_SMEM ((3 * BQ * QSTR + BQ * PSTR) * 4)   // 118784 bytes

__global__ __launch_bounds__(256) void attn_kernel() {
    int qb  = (int)(gridDim.x - 1) - (int)blockIdx.x;   // longest blocks first
    int h   = blockIdx.y;
    int kvh = h >> 2;
    extern __shared__ float smbuf[];
    float* Qs = smbuf;
    float* Ks = Qs + BQ * QSTR;
    float* Vs = Ks + BQ * QSTR;
    float* Ps = Vs + BQ * QSTR;

    int tid = threadIdx.x;
    int ty = tid >> 4;   // 0..15 -> rows ty*4..+3
    int tx = tid & 15;   // 0..15 -> S cols tx*4..+3, O cols tx*4 & 64+tx*4
    const float inv_scale = 0.08838834764831845f;  // 1/sqrt(128)

    // load Q tile
    {
        int r  = tid >> 2;
        int c0 = (tid & 3) * 4;
        const float* qrow = g_qkv + (size_t)(qb * BQ + r) * NCOLS + h * DHEAD;
        #pragma unroll
        for (int jj = 0; jj < 8; jj++)
            *(float4*)&Qs[r * QSTR + c0 + jj * 16] = *(const float4*)(qrow + c0 + jj * 16);
    }

    float acc[4][8];
    float mrow[4], lrow[4];
    #pragma unroll
    for (int i = 0; i < 4; i++) {
        mrow[i] = -1e30f; lrow[i] = 0.f;
        #pragma unroll
        for (int j = 0; j < 8; j++) acc[i][j] = 0.f;
    }

    for (int kb = 0; kb <= qb; kb++) {
        __syncthreads();   // prev PV done before K/V overwrite; also covers Q load
        {
            int r  = tid >> 2;
            int c0 = (tid & 3) * 4;
            const float* krow = g_qkv + (size_t)(kb * BKV + r) * NCOLS + 2048 + kvh * DHEAD;
            const float* vrow = krow + 512;
            #pragma unroll
            for (int jj = 0; jj < 8; jj++) {
                *(float4*)&Ks[r * QSTR + c0 + jj * 16] = *(const float4*)(krow + c0 + jj * 16);
                *(float4*)&Vs[r * QSTR + c0 + jj * 16] = *(const float4*)(vrow + c0 + jj * 16);
            }
        }
        __syncthreads();

        // S = Q K^T  (4x4 per thread)
        float s[4][4];
        #pragma unroll
        for (int i = 0; i < 4; i++)
            #pragma unroll
            for (int j = 0; j < 4; j++) s[i][j] = 0.f;

        #pragma unroll 8
        for (int k = 0; k < DHEAD; k += 4) {
            float4 q4[4], k4[4];
            #pragma unroll
            for (int i = 0; i < 4; i++) q4[i] = *(const float4*)&Qs[(ty * 4 + i) * QSTR + k];
            #pragma unroll
            for (int j = 0; j < 4; j++) k4[j] = *(const float4*)&Ks[(tx * 4 + j) * QSTR + k];
            #pragma unroll
            for (int i = 0; i < 4; i++)
                #pragma unroll
                for (int j = 0; j < 4; j++) {
                    s[i][j] = fmaf(q4[i].x, k4[j].x, s[i][j]);
                    s[i][j] = fmaf(q4[i].y, k4[j].y, s[i][j]);
                    s[i][j] = fmaf(q4[i].z, k4[j].z, s[i][j]);
                    s[i][j] = fmaf(q4[i].w, k4[j].w, s[i][j]);
                }
        }

        bool diag = (kb == qb);
        #pragma unroll
        for (int i = 0; i < 4; i++) {
            int grow = ty * 4 + i;
            float mt = -1e30f;
            #pragma unroll
            for (int j = 0; j < 4; j++) {
                float v = s[i][j] * inv_scale;
                if (diag && (tx * 4 + j > grow)) v = -1e30f;
                s[i][j] = v;
                mt = fmaxf(mt, v);
            }
            #pragma unroll
            for (int o = 8; o > 0; o >>= 1)
                mt = fmaxf(mt, __shfl_xor_sync(0xffffffffu, mt, o));
            float mnew  = fmaxf(mrow[i], mt);
            float alpha = __expf(mrow[i] - mnew);
            float psum = 0.f;
            #pragma unroll
            for (int j = 0; j < 4; j++) {
                float p = __expf(s[i][j] - mnew);
                psum += p;
                Ps[grow * PSTR + tx * 4 + j] = p;
            }
            #pragma unroll
            for (int o = 8; o > 0; o >>= 1)
                psum += __shfl_xor_sync(0xffffffffu, psum, o);
            lrow[i] = lrow[i] * alpha + psum;
            mrow[i] = mnew;
            #pragma unroll
            for (int j = 0; j < 8; j++) acc[i][j] *= alpha;
        }
        __syncthreads();   // Ps visible to everyone

        // O += P V
        #pragma unroll 4
        for (int kk = 0; kk < BKV; kk++) {
            float4 v0 = *(const float4*)&Vs[kk * QSTR + tx * 4];
            float4 v1 = *(const float4*)&Vs[kk * QSTR + 64 + tx * 4];
            float p[4];
            #pragma unroll
            for (int i = 0; i < 4; i++) p[i] = Ps[(ty * 4 + i) * PSTR + kk];
            #pragma unroll
            for (int i = 0; i < 4; i++) {
                acc[i][0] = fmaf(p[i], v0.x, acc[i][0]);
                acc[i][1] = fmaf(p[i], v0.y, acc[i][1]);
                acc[i][2] = fmaf(p[i], v0.z, acc[i][2]);
                acc[i][3] = fmaf(p[i], v0.w, acc[i][3]);
                acc[i][4] = fmaf(p[i], v1.x, acc[i][4]);
                acc[i][5] = fmaf(p[i], v1.y, acc[i][5]);
                acc[i][6] = fmaf(p[i], v1.z, acc[i][6]);
                acc[i][7] = fmaf(p[i], v1.w, acc[i][7]);
            }
        }
    }

    // normalize + write z
    #pragma unroll
    for (int i = 0; i < 4; i++) {
        float invl = 1.0f / lrow[i];
        size_t base = (size_t)(qb * BQ + ty * 4 + i) * DMODEL + h * DHEAD;
        float4 o0 = make_float4(acc[i][0] * invl, acc[i][1] * invl,
                                acc[i][2] * invl, acc[i][3] * invl);
        float4 o1 = make_float4(acc[i][4] * invl, acc[i][5] * invl,
                                acc[i][6] * invl, acc[i][7] * invl);
        *(float4*)&g_z[base + tx * 4]      = o0;
        *(float4*)&g_z[base + 64 + tx * 4] = o1;
    }
}

// ---------------- launcher ----------------
extern "C" void kernel_launch(void* const* d_in, const int* in_sizes, int n_in,
                              void* d_out, int out_size) {
    const float* x  = (const float*)d_in[0];
    const float* WQ = (const float*)d_in[1];
    const float* WK = (const float*)d_in[2];
    const float* WV = (const float*)d_in[3];
    const float* WO = (const float*)d_in[4];
    const float* bQ = (const float*)d_in[5];
    const float* bK = (const float*)d_in[6];
    const float* bV = (const float*)d_in[7];
    const float* bO = (const float*)d_in[8];
    float* out = (float*)d_out;

    float *Wcat, *bcat, *qkv, *z;
    cudaGetSymbolAddress((void**)&Wcat, g_Wcat);
    cudaGetSymbolAddress((void**)&bcat, g_bcat);
    cudaGetSymbolAddress((void**)&qkv,  g_qkv);
    cudaGetSymbolAddress((void**)&z,    g_z);

    cudaFuncSetAttribute(attn_kernel, cudaFuncAttributeMaxDynamicSharedMemorySize, ATTN_SMEM);

    // 1) repack QKV weights + bias concat
    {
        int total = DMODEL * NCOLS;
        repack_kernel<<<(total + 255) / 256, 256>>>(WQ, WK, WV, bQ, bK, bV);
    }
    // 2) QKV projection: [4096,2048] x [2048,3072]
    {
        dim3 grid(NCOLS / BN, SEQ / BM);
        sgemm_bias<<<grid, 256>>>(x, Wcat, bcat, qkv, SEQ, NCOLS, DMODEL);
    }
    // 3) rotary on q and k
    {
        int total = SEQ * 20 * 64;
        rotary_kernel<<<(total + 255) / 256, 256>>>();
    }
    // 4) causal flash attention -> z
    {
        dim3 grid(SEQ / BQ, NH);
        attn_kernel<<<grid, 256, ATTN_SMEM>>>();
    }
    // 5) output projection: z[4096,2048] x WO[2048,2048] + bO
    {
        dim3 grid(DMODEL / BN, SEQ / BM);
        sgemm_bias<<<grid, 256>>>(z, WO, bO, out, SEQ, DMODEL, DMODEL);
    }
}

// round 3
// speedup vs baseline: 1.2201x; 1.2201x over previous
#include <cuda_runtime.h>
#include <cuda_bf16.h>
#include <math.h>
#include <stdint.h>

// Problem constants (fixed shapes)
#define SEQ     4096
#define DMODEL  2048
#define DHEAD   128
#define NH      16
#define NKV     4
#define NCOLS   3072   // 16*128 (Q) + 4*128 (K) + 4*128 (V)
#define KDIM    2048

// ---------------- scratch (static __device__, no allocation) ----------------
__device__ __align__(256) float g_bcat[NCOLS];
__device__ __align__(256) float g_qkv[SEQ * NCOLS];
__device__ __align__(256) float g_z[SEQ * DMODEL];
__device__ __align__(256) __nv_bfloat16 g_xhi[SEQ * DMODEL];
__device__ __align__(256) __nv_bfloat16 g_xlo[SEQ * DMODEL];
__device__ __align__(256) __nv_bfloat16 g_zhi[SEQ * DMODEL];
__device__ __align__(256) __nv_bfloat16 g_zlo[SEQ * DMODEL];
__device__ __align__(256) __nv_bfloat16 g_Wthi[NCOLS * KDIM];   // QKV W^T [N=3072][K=2048]
__device__ __align__(256) __nv_bfloat16 g_Wtlo[NCOLS * KDIM];
__device__ __align__(256) __nv_bfloat16 g_WOthi[DMODEL * KDIM]; // W_O^T [2048][2048]
__device__ __align__(256) __nv_bfloat16 g_WOtlo[DMODEL * KDIM];

// ---------------- helpers ----------------
__device__ __forceinline__ uint32_t smem_u32(const void* p) {
    uint32_t a;
    asm("{ .reg .u64 t; cvta.to.shared.u64 t, %1; cvt.u32.u64 %0, t; }" : "=r"(a) : "l"(p));
    return a;
}
__device__ __forceinline__ void cp16(uint32_t s, const void* g) {
    asm volatile("cp.async.cg.shared.global [%0], [%1], 16;" :: "r"(s), "l"(g));
}
#define CP_COMMIT() asm volatile("cp.async.commit_group;" ::: "memory")
__device__ __forceinline__ void ldsm4(uint32_t* r, uint32_t addr) {
    asm volatile("ldmatrix.sync.aligned.m8n8.x4.shared.b16 {%0,%1,%2,%3}, [%4];"
        : "=r"(r[0]), "=r"(r[1]), "=r"(r[2]), "=r"(r[3]) : "r"(addr));
}
__device__ __forceinline__ void mma_bf16(float* d, const uint32_t* a, const uint32_t* b) {
    asm volatile("mma.sync.aligned.m16n8k16.row.col.f32.bf16.bf16.f32 "
        "{%0,%1,%2,%3}, {%4,%5,%6,%7}, {%8,%9}, {%0,%1,%2,%3};"
        : "+f"(d[0]), "+f"(d[1]), "+f"(d[2]), "+f"(d[3])
        : "r"(a[0]), "r"(a[1]), "r"(a[2]), "r"(a[3]), "r"(b[0]), "r"(b[1]));
}
#define SWZ(off) ((off) ^ (((off) >> 3) & 0x70))

// ---------------- weight repack (QKV, transposed, bf16 split) + bias ----------------
__global__ void repack_wqkv(const float* __restrict__ WQ, const float* __restrict__ WK,
                            const float* __restrict__ WV, const float* __restrict__ bQ,
                            const float* __restrict__ bK, const float* __restrict__ bV) {
    int idx = blockIdx.x * blockDim.x + threadIdx.x;
    if (idx < NCOLS) {
        float b;
        if      (idx < 2048) b = bQ[idx];
        else if (idx < 2560) b = bK[idx - 2048];
        else                 b = bV[idx - 2560];
        g_bcat[idx] = b;
    }
    if (idx >= NCOLS * KDIM) return;
    int n = idx >> 11;
    int k = idx & 2047;
    float v;
    if (n < 2048) {
        int head = n >> 7, h = n & 127;
        v = WQ[((size_t)head * KDIM + k) * DHEAD + h];
    } else if (n < 2560) {
        int head = (n - 2048) >> 7, h = n & 127;
        v = WK[((size_t)head * KDIM + k) * DHEAD + h];
    } else {
        int head = (n - 2560) >> 7, h = n & 127;
        v = WV[((size_t)head * KDIM + k) * DHEAD + h];
    }
    __nv_bfloat16 hi = __float2bfloat16(v);
    float r = v - __bfloat162float(hi);
    g_Wthi[idx] = hi;
    g_Wtlo[idx] = __float2bfloat16(r);
}

__global__ void repack_wo(const float* __restrict__ WO) {
    int idx = blockIdx.x * blockDim.x + threadIdx.x;   // idx = k*2048 + m (coalesced read)
    if (idx >= DMODEL * KDIM) return;
    int k = idx >> 11;
    int m = idx & 2047;
    float v = WO[idx];
    __nv_bfloat16 hi = __float2bfloat16(v);
    float r = v - __bfloat162float(hi);
    g_WOthi[(size_t)m * KDIM + k] = hi;
    g_WOtlo[(size_t)m * KDIM + k] = __float2bfloat16(r);
}

__global__ void split_f32(const float* __restrict__ src, __nv_bfloat16* __restrict__ hi,
                          __nv_bfloat16* __restrict__ lo, int n) {
    int i = blockIdx.x * blockDim.x + threadIdx.x;
    if (i >= n) return;
    float v = src[i];
    __nv_bfloat16 h = __float2bfloat16(v);
    float r = v - __bfloat162float(h);
    hi[i] = h;
    lo[i] = __float2bfloat16(r);
}

// ---------------- mma.sync bf16x3 GEMM: C[M,N] = A[M,2048] * B^T + bias ----------------
// A hi/lo row-major [M][2048]; B hi/lo transposed row-major [N][2048].
#define BM 128
#define BN 128
#define BKT 64                 // K elems per stage
#define MATB 16384             // 128 x 64 x 2B
#define BUFB (4 * MATB)        // Ahi|Alo|Bhi|Blo per stage = 64 KB
#define GSMEM (2 * BUFB)       // double buffered = 128 KB
#define NSTG (KDIM / BKT)      // 32

__device__ __forceinline__ void load_stage(uint32_t smb, int s, int m0, int n0, int tid,
                                           const __nv_bfloat16* Ahi, const __nv_bfloat16* Alo,
                                           const __nv_bfloat16* Bhi, const __nv_bfloat16* Blo) {
    uint32_t bb = smb + (s & 1) * BUFB;
    int k0 = s * BKT;
    #pragma unroll
    for (int i = 0; i < 4; i++) {
        int c = tid + i * 256;        // 0..1023
        int r = c >> 3, ch = c & 7;
        uint32_t so = bb + SWZ(r * 128 + ch * 16);
        size_t ga = (size_t)(m0 + r) * KDIM + k0 + ch * 8;
        size_t gb = (size_t)(n0 + r) * KDIM + k0 + ch * 8;
        cp16(so,            Ahi + ga);
        cp16(so + MATB,     Alo + ga);
        cp16(so + 2 * MATB, Bhi + gb);
        cp16(so + 3 * MATB, Blo + gb);
    }
}

__global__ __launch_bounds__(256, 1) void gemm_mma_x3(
    const __nv_bfloat16* __restrict__ Ahi, const __nv_bfloat16* __restrict__ Alo,
    const __nv_bfloat16* __restrict__ Bhi, const __nv_bfloat16* __restrict__ Blo,
    const float* __restrict__ bias, float* __restrict__ C, int N)
{
    extern __shared__ char sm[];
    const uint32_t smb = smem_u32(sm);
    const int tid = threadIdx.x;
    const int wid = tid >> 5, lid = tid & 31;
    const int m0 = blockIdx.x * BM, n0 = blockIdx.y * BN;
    const int wm = (wid & 1) * 64;     // warp M offset
    const int wn = (wid >> 1) * 32;    // warp N offset

    float acc[4][4][4];
    #pragma unroll
    for (int i = 0; i < 4; i++)
        #pragma unroll
        for (int j = 0; j < 4; j++)
            #pragma unroll
            for (int k = 0; k < 4; k++) acc[i][j][k] = 0.f;

    // per-lane ldmatrix address components
    const int arow = lid & 15;               // A: row within m16
    const int asel = (lid >> 4) * 16;        // A: k-halves (bytes)
    const int brow = ((lid >> 4) << 3) + (lid & 7);  // B: n within n16
    const int bsel = ((lid >> 3) & 1) * 16;          // B: k-halves (bytes)

    load_stage(smb, 0, m0, n0, tid, Ahi, Alo, Bhi, Blo);
    CP_COMMIT();

    for (int s = 0; s < NSTG; s++) {
        if (s + 1 < NSTG) {
            load_stage(smb, s + 1, m0, n0, tid, Ahi, Alo, Bhi, Blo);
            CP_COMMIT();
            asm volatile("cp.async.wait_group 1;" ::: "memory");
        } else {
            asm volatile("cp.async.wait_group 0;" ::: "memory");
        }
        __syncthreads();

        uint32_t bb = smb + (s & 1) * BUFB;
        #pragma unroll
        for (int kk = 0; kk < 4; kk++) {
            uint32_t ah[4][4], al[4][4];
            #pragma unroll
            for (int ms = 0; ms < 4; ms++) {
                uint32_t off = SWZ((wm + ms * 16 + arow) * 128 + kk * 32 + asel);
                ldsm4(ah[ms], bb + off);
                ldsm4(al[ms], bb + MATB + off);
            }
            uint32_t bh[2][4], bl[2][4];
            #pragma unroll
            for (int ns = 0; ns < 2; ns++) {
                uint32_t off = SWZ((wn + ns * 16 + brow) * 128 + kk * 32 + bsel);
                ldsm4(bh[ns], bb + 2 * MATB + off);
                ldsm4(bl[ns], bb + 3 * MATB + off);
            }
            #pragma unroll
            for (int ms = 0; ms < 4; ms++)
                #pragma unroll
                for (int n8 = 0; n8 < 4; n8++) {
                    const uint32_t* ph = &bh[n8 >> 1][(n8 & 1) * 2];
                    const uint32_t* pl = &bl[n8 >> 1][(n8 & 1) * 2];
                    mma_bf16(acc[ms][n8], ah[ms], ph);
                    mma_bf16(acc[ms][n8], ah[ms], pl);
                    mma_bf16(acc[ms][n8], al[ms], ph);
                }
        }
        __syncthreads();
    }

    // epilogue: fragment rows (l>>2, +8), col pair (l&3)*2
    const int erow = lid >> 2, ecol = (lid & 3) * 2;
    #pragma unroll
    for (int ms = 0; ms < 4; ms++) {
        int r0 = m0 + wm + ms * 16 + erow;
        #pragma unroll
        for (int n8 = 0; n8 < 4; n8++) {
            int c = n0 + wn + n8 * 8 + ecol;
            float2 bv = *(const float2*)&bias[c];
            float2 o0 = make_float2(acc[ms][n8][0] + bv.x, acc[ms][n8][1] + bv.y);
            float2 o1 = make_float2(acc[ms][n8][2] + bv.x, acc[ms][n8][3] + bv.y);
            *(float2*)&C[(size_t)r0 * N + c]       = o0;
            *(float2*)&C[(size_t)(r0 + 8) * N + c] = o1;
        }
    }
}

// ---------------- rotary (interleaved pairs, full head dim) ----------------
__global__ void rotary_kernel() {
    int idx = blockIdx.x * blockDim.x + threadIdx.x;
    const int total = SEQ * 20 * 64;
    if (idx >= total) return;
    int j    = idx & 63;
    int rest = idx >> 6;
    int head = rest % 20;
    int s    = rest / 20;
    double dfreq = pow(10000.0, -(double)j / 64.0);
    float  freq  = (float)dfreq;
    float  angle = (float)s * freq;
    double da = (double)angle;
    float c  = (float)cos(da);
    float sn = (float)sin(da);
    int off = (head < 16) ? head * 128 : 2048 + (head - 16) * 128;
    float* p = g_qkv + (size_t)s * NCOLS + off + 2 * j;
    float x1 = p[0], x2 = p[1];
    p[0] = x1 * c  - x2 * sn;
    p[1] = x1 * sn + x2 * c;
}

// ---------------- flash attention (causal, fp32) — unchanged from R1 ----------------
#define BQ   64
#define BKV  64
#define QSTR 132
#define PSTR 68
#define ATTN_SMEM ((3 * BQ * QSTR + BQ * PSTR) * 4)

__global__ __launch_bounds__(256) void attn_kernel() {
    int qb  = (int)(gridDim.x - 1) - (int)blockIdx.x;
    int h   = blockIdx.y;
    int kvh = h >> 2;
    extern __shared__ float smbuf[];
    float* Qs = smbuf;
    float* Ks = Qs + BQ * QSTR;
    float* Vs = Ks + BQ * QSTR;
    float* Ps = Vs + BQ * QSTR;

    int tid = threadIdx.x;
    int ty = tid >> 4;
    int tx = tid & 15;
    const float inv_scale = 0.08838834764831845f;

    {
        int r  = tid >> 2;
        int c0 = (tid & 3) * 4;
        const float* qrow = g_qkv + (size_t)(qb * BQ + r) * NCOLS + h * DHEAD;
        #pragma unroll
        for (int jj = 0; jj < 8; jj++)
            *(float4*)&Qs[r * QSTR + c0 + jj * 16] = *(const float4*)(qrow + c0 + jj * 16);
    }

    float acc[4][8];
    float mrow[4], lrow[4];
    #pragma unroll
    for (int i = 0; i < 4; i++) {
        mrow[i] = -1e30f; lrow[i] = 0.f;
        #pragma unroll
        for (int j = 0; j < 8; j++) acc[i][j] = 0.f;
    }

    for (int kb = 0; kb <= qb; kb++) {
        __syncthreads();
        {
            int r  = tid >> 2;
            int c0 = (tid & 3) * 4;
            const float* krow = g_qkv + (size_t)(kb * BKV + r) * NCOLS + 2048 + kvh * DHEAD;
            const float* vrow = krow + 512;
            #pragma unroll
            for (int jj = 0; jj < 8; jj++) {
                *(float4*)&Ks[r * QSTR + c0 + jj * 16] = *(const float4*)(krow + c0 + jj * 16);
                *(float4*)&Vs[r * QSTR + c0 + jj * 16] = *(const float4*)(vrow + c0 + jj * 16);
            }
        }
        __syncthreads();

        float s[4][4];
        #pragma unroll
        for (int i = 0; i < 4; i++)
            #pragma unroll
            for (int j = 0; j < 4; j++) s[i][j] = 0.f;

        #pragma unroll 8
        for (int k = 0; k < DHEAD; k += 4) {
            float4 q4[4], k4[4];
            #pragma unroll
            for (int i = 0; i < 4; i++) q4[i] = *(const float4*)&Qs[(ty * 4 + i) * QSTR + k];
            #pragma unroll
            for (int j = 0; j < 4; j++) k4[j] = *(const float4*)&Ks[(tx * 4 + j) * QSTR + k];
            #pragma unroll
            for (int i = 0; i < 4; i++)
                #pragma unroll
                for (int j = 0; j < 4; j++) {
                    s[i][j] = fmaf(q4[i].x, k4[j].x, s[i][j]);
                    s[i][j] = fmaf(q4[i].y, k4[j].y, s[i][j]);
                    s[i][j] = fmaf(q4[i].z, k4[j].z, s[i][j]);
                    s[i][j] = fmaf(q4[i].w, k4[j].w, s[i][j]);
                }
        }

        bool diag = (kb == qb);
        #pragma unroll
        for (int i = 0; i < 4; i++) {
            int grow = ty * 4 + i;
            float mt = -1e30f;
            #pragma unroll
            for (int j = 0; j < 4; j++) {
                float v = s[i][j] * inv_scale;
                if (diag && (tx * 4 + j > grow)) v = -1e30f;
                s[i][j] = v;
                mt = fmaxf(mt, v);
            }
            #pragma unroll
            for (int o = 8; o > 0; o >>= 1)
                mt = fmaxf(mt, __shfl_xor_sync(0xffffffffu, mt, o));
            float mnew  = fmaxf(mrow[i], mt);
            float alpha = __expf(mrow[i] - mnew);
            float psum = 0.f;
            #pragma unroll
            for (int j = 0; j < 4; j++) {
                float p = __expf(s[i][j] - mnew);
                psum += p;
                Ps[grow * PSTR + tx * 4 + j] = p;
            }
            #pragma unroll
            for (int o = 8; o > 0; o >>= 1)
                psum += __shfl_xor_sync(0xffffffffu, psum, o);
            lrow[i] = lrow[i] * alpha + psum;
            mrow[i] = mnew;
            #pragma unroll
            for (int j = 0; j < 8; j++) acc[i][j] *= alpha;
        }
        __syncthreads();

        #pragma unroll 4
        for (int kk = 0; kk < BKV; kk++) {
            float4 v0 = *(const float4*)&Vs[kk * QSTR + tx * 4];
            float4 v1 = *(const float4*)&Vs[kk * QSTR + 64 + tx * 4];
            float p[4];
            #pragma unroll
            for (int i = 0; i < 4; i++) p[i] = Ps[(ty * 4 + i) * PSTR + kk];
            #pragma unroll
            for (int i = 0; i < 4; i++) {
                acc[i][0] = fmaf(p[i], v0.x, acc[i][0]);
                acc[i][1] = fmaf(p[i], v0.y, acc[i][1]);
                acc[i][2] = fmaf(p[i], v0.z, acc[i][2]);
                acc[i][3] = fmaf(p[i], v0.w, acc[i][3]);
                acc[i][4] = fmaf(p[i], v1.x, acc[i][4]);
                acc[i][5] = fmaf(p[i], v1.y, acc[i][5]);
                acc[i][6] = fmaf(p[i], v1.z, acc[i][6]);
                acc[i][7] = fmaf(p[i], v1.w, acc[i][7]);
            }
        }
    }

    #pragma unroll
    for (int i = 0; i < 4; i++) {
        float invl = 1.0f / lrow[i];
        size_t base = (size_t)(qb * BQ + ty * 4 + i) * DMODEL + h * DHEAD;
        float4 o0 = make_float4(acc[i][0] * invl, acc[i][1] * invl,
                                acc[i][2] * invl, acc[i][3] * invl);
        float4 o1 = make_float4(acc[i][4] * invl, acc[i][5] * invl,
                                acc[i][6] * invl, acc[i][7] * invl);
        *(float4*)&g_z[base + tx * 4]      = o0;
        *(float4*)&g_z[base + 64 + tx * 4] = o1;
    }
}

// ---------------- launcher ----------------
extern "C" void kernel_launch(void* const* d_in, const int* in_sizes, int n_in,
                              void* d_out, int out_size) {
    const float* x  = (const float*)d_in[0];
    const float* WQ = (const float*)d_in[1];
    const float* WK = (const float*)d_in[2];
    const float* WV = (const float*)d_in[3];
    const float* WO = (const float*)d_in[4];
    const float* bQ = (const float*)d_in[5];
    const float* bK = (const float*)d_in[6];
    const float* bV = (const float*)d_in[7];
    const float* bO = (const float*)d_in[8];
    float* out = (float*)d_out;

    float *bcat, *qkv, *z;
    __nv_bfloat16 *xhi, *xlo, *zhi, *zlo, *Wthi, *Wtlo, *WOthi, *WOtlo;
    cudaGetSymbolAddress((void**)&bcat,  g_bcat);
    cudaGetSymbolAddress((void**)&qkv,   g_qkv);
    cudaGetSymbolAddress((void**)&z,     g_z);
    cudaGetSymbolAddress((void**)&xhi,   g_xhi);
    cudaGetSymbolAddress((void**)&xlo,   g_xlo);
    cudaGetSymbolAddress((void**)&zhi,   g_zhi);
    cudaGetSymbolAddress((void**)&zlo,   g_zlo);
    cudaGetSymbolAddress((void**)&Wthi,  g_Wthi);
    cudaGetSymbolAddress((void**)&Wtlo,  g_Wtlo);
    cudaGetSymbolAddress((void**)&WOthi, g_WOthi);
    cudaGetSymbolAddress((void**)&WOtlo, g_WOtlo);

    cudaFuncSetAttribute(attn_kernel, cudaFuncAttributeMaxDynamicSharedMemorySize, ATTN_SMEM);
    cudaFuncSetAttribute(gemm_mma_x3, cudaFuncAttributeMaxDynamicSharedMemorySize, GSMEM);

    // 1) weight repacks + input split
    repack_wqkv<<<(NCOLS * KDIM + 255) / 256, 256>>>(WQ, WK, WV, bQ, bK, bV);
    repack_wo<<<(DMODEL * KDIM + 255) / 256, 256>>>(WO);
    split_f32<<<(SEQ * DMODEL + 255) / 256, 256>>>(x, xhi, xlo, SEQ * DMODEL);

    // 2) QKV projection: [4096,2048] x [2048,3072]^T on HMMA
    {
        dim3 grid(SEQ / BM, NCOLS / BN);
        gemm_mma_x3<<<grid, 256, GSMEM>>>(xhi, xlo, Wthi, Wtlo, bcat, qkv, NCOLS);
    }
    // 3) rotary on q and k
    rotary_kernel<<<(SEQ * 20 * 64 + 255) / 256, 256>>>();
    // 4) causal flash attention -> z
    {
        dim3 grid(SEQ / BQ, NH);
        attn_kernel<<<grid, 256, ATTN_SMEM>>>();
    }
    // 5) split z, O-projection on HMMA
    split_f32<<<(SEQ * DMODEL + 255) / 256, 256>>>(z, zhi, zlo, SEQ * DMODEL);
    {
        dim3 grid(SEQ / BM, DMODEL / BN);
        gemm_mma_x3<<<grid, 256, GSMEM>>>(zhi, zlo, WOthi, WOtlo, bO, out, DMODEL);
    }
}

// round 4
// speedup vs baseline: 4.5544x; 3.7327x over previous
#include <cuda_runtime.h>
#include <cuda_bf16.h>
#include <math.h>
#include <stdint.h>

// Problem constants (fixed shapes)
#define SEQ     4096
#define DMODEL  2048
#define DHEAD   128
#define NH      16
#define NKV     4
#define NCOLS   3072   // 16*128 (Q) + 4*128 (K) + 4*128 (V)
#define KDIM    2048

// ---------------- scratch (static __device__, no allocation) ----------------
__device__ __align__(256) float g_bcat[NCOLS];
__device__ __align__(256) float g_qkv[SEQ * NCOLS];
__device__ __align__(256) __nv_bfloat16 g_xhi[SEQ * DMODEL];
__device__ __align__(256) __nv_bfloat16 g_xlo[SEQ * DMODEL];
__device__ __align__(256) __nv_bfloat16 g_zhi[SEQ * DMODEL];
__device__ __align__(256) __nv_bfloat16 g_zlo[SEQ * DMODEL];
__device__ __align__(256) __nv_bfloat16 g_Wthi[NCOLS * KDIM];   // QKV W^T [N=3072][K=2048]
__device__ __align__(256) __nv_bfloat16 g_Wtlo[NCOLS * KDIM];
__device__ __align__(256) __nv_bfloat16 g_WOthi[DMODEL * KDIM]; // W_O^T [2048][2048]
__device__ __align__(256) __nv_bfloat16 g_WOtlo[DMODEL * KDIM];
// attention operands (post-rotary, bf16 hi/lo splits)
__device__ __align__(256) __nv_bfloat16 g_qbhi[SEQ * DMODEL];
__device__ __align__(256) __nv_bfloat16 g_qblo[SEQ * DMODEL];
__device__ __align__(256) __nv_bfloat16 g_kbhi[NKV * SEQ * DHEAD];
__device__ __align__(256) __nv_bfloat16 g_kblo[NKV * SEQ * DHEAD];
__device__ __align__(256) __nv_bfloat16 g_vthi[NKV * DHEAD * SEQ];   // V transposed [kvh][dh][s]
__device__ __align__(256) __nv_bfloat16 g_vtlo[NKV * DHEAD * SEQ];
__device__ __align__(256) float g_rcos[SEQ * 64];
__device__ __align__(256) float g_rsin[SEQ * 64];

// ---------------- helpers ----------------
__device__ __forceinline__ uint32_t smem_u32(const void* p) {
    uint32_t a;
    asm("{ .reg .u64 t; cvta.to.shared.u64 t, %1; cvt.u32.u64 %0, t; }" : "=r"(a) : "l"(p));
    return a;
}
__device__ __forceinline__ void cp16(uint32_t s, const void* g) {
    asm volatile("cp.async.cg.shared.global [%0], [%1], 16;" :: "r"(s), "l"(g));
}
#define CP_COMMIT() asm volatile("cp.async.commit_group;" ::: "memory")
__device__ __forceinline__ void ldsm4(uint32_t* r, uint32_t addr) {
    asm volatile("ldmatrix.sync.aligned.m8n8.x4.shared.b16 {%0,%1,%2,%3}, [%4];"
        : "=r"(r[0]), "=r"(r[1]), "=r"(r[2]), "=r"(r[3]) : "r"(addr));
}
__device__ __forceinline__ void mma_bf16(float* d, const uint32_t* a, const uint32_t* b) {
    asm volatile("mma.sync.aligned.m16n8k16.row.col.f32.bf16.bf16.f32 "
        "{%0,%1,%2,%3}, {%4,%5,%6,%7}, {%8,%9}, {%0,%1,%2,%3};"
        : "+f"(d[0]), "+f"(d[1]), "+f"(d[2]), "+f"(d[3])
        : "r"(a[0]), "r"(a[1]), "r"(a[2]), "r"(a[3]), "r"(b[0]), "r"(b[1]));
}
__device__ __forceinline__ float ex2f(float x) {
    float y; asm("ex2.approx.ftz.f32 %0, %1;" : "=f"(y) : "f"(x)); return y;
}
__device__ __forceinline__ void split2(float p0, float p1, uint32_t& hi, uint32_t& lo) {
    __nv_bfloat16 h0 = __float2bfloat16(p0), h1 = __float2bfloat16(p1);
    float r0 = p0 - __bfloat162float(h0), r1 = p1 - __bfloat162float(h1);
    __nv_bfloat16 e0 = __float2bfloat16(r0), e1 = __float2bfloat16(r1);
    hi = ((uint32_t)__bfloat16_as_ushort(h1) << 16) | (uint32_t)__bfloat16_as_ushort(h0);
    lo = ((uint32_t)__bfloat16_as_ushort(e1) << 16) | (uint32_t)__bfloat16_as_ushort(e0);
}
__device__ __forceinline__ void split1(float v, __nv_bfloat16& h, __nv_bfloat16& l) {
    h = __float2bfloat16(v);
    l = __float2bfloat16(v - __bfloat162float(h));
}
#define SWZ(off) ((off) ^ (((off) >> 3) & 0x70))

// ---------------- weight repack (QKV, transposed, bf16 split) + bias ----------------
__global__ void repack_wqkv(const float* __restrict__ WQ, const float* __restrict__ WK,
                            const float* __restrict__ WV, const float* __restrict__ bQ,
                            const float* __restrict__ bK, const float* __restrict__ bV) {
    int idx = blockIdx.x * blockDim.x + threadIdx.x;
    if (idx < NCOLS) {
        float b;
        if      (idx < 2048) b = bQ[idx];
        else if (idx < 2560) b = bK[idx - 2048];
        else                 b = bV[idx - 2560];
        g_bcat[idx] = b;
    }
    if (idx >= NCOLS * KDIM) return;
    int n = idx >> 11;
    int k = idx & 2047;
    float v;
    if (n < 2048) {
        int head = n >> 7, h = n & 127;
        v = WQ[((size_t)head * KDIM + k) * DHEAD + h];
    } else if (n < 2560) {
        int head = (n - 2048) >> 7, h = n & 127;
        v = WK[((size_t)head * KDIM + k) * DHEAD + h];
    } else {
        int head = (n - 2560) >> 7, h = n & 127;
        v = WV[((size_t)head * KDIM + k) * DHEAD + h];
    }
    __nv_bfloat16 hi, lo;
    split1(v, hi, lo);
    g_Wthi[idx] = hi;
    g_Wtlo[idx] = lo;
}

__global__ void repack_wo(const float* __restrict__ WO) {
    int idx = blockIdx.x * blockDim.x + threadIdx.x;
    if (idx >= DMODEL * KDIM) return;
    int k = idx >> 11;
    int m = idx & 2047;
    __nv_bfloat16 hi, lo;
    split1(WO[idx], hi, lo);
    g_WOthi[(size_t)m * KDIM + k] = hi;
    g_WOtlo[(size_t)m * KDIM + k] = lo;
}

__global__ void split_f32(const float* __restrict__ src, __nv_bfloat16* __restrict__ hi,
                          __nv_bfloat16* __restrict__ lo, int n) {
    int i = blockIdx.x * blockDim.x + threadIdx.x;
    if (i >= n) return;
    __nv_bfloat16 h, l;
    split1(src[i], h, l);
    hi[i] = h;
    lo[i] = l;
}

// ---------------- rotary table (double precision, validated path) ----------------
__global__ void rotab_kernel() {
    int idx = blockIdx.x * blockDim.x + threadIdx.x;
    if (idx >= SEQ * 64) return;
    int j = idx & 63, s = idx >> 6;
    double dfreq = pow(10000.0, -(double)j / 64.0);
    float freq = (float)dfreq;
    float angle = (float)s * freq;
    double da = (double)angle;
    g_rcos[idx] = (float)cos(da);
    g_rsin[idx] = (float)sin(da);
}

// ---------------- rotary + bf16 hi/lo preconvert of q, k, v ----------------
// grid (6, 4096), block 256: p in [0,1536), s = blockIdx.y
__global__ void preconvert() {
    int p = blockIdx.x * 256 + threadIdx.x;
    int s = blockIdx.y;
    int j = p & 63;
    if (p < 1280) {
        float c  = g_rcos[s * 64 + j];
        float sn = g_rsin[s * 64 + j];
        int head = (p < 1024) ? (p >> 6) : ((p - 1024) >> 6);
        const float* src = g_qkv + (size_t)s * NCOLS +
                           ((p < 1024) ? head * 128 : 2048 + head * 128) + 2 * j;
        float x1 = src[0], x2 = src[1];
        float o1 = x1 * c - x2 * sn;
        float o2 = x1 * sn + x2 * c;
        __nv_bfloat16 h1, l1, h2, l2;
        split1(o1, h1, l1);
        split1(o2, h2, l2);
        if (p < 1024) {
            size_t o = (size_t)s * 2048 + head * 128 + 2 * j;
            g_qbhi[o] = h1; g_qbhi[o + 1] = h2;
            g_qblo[o] = l1; g_qblo[o + 1] = l2;
        } else {
            size_t o = ((size_t)head * SEQ + s) * DHEAD + 2 * j;
            g_kbhi[o] = h1; g_kbhi[o + 1] = h2;
            g_kblo[o] = l1; g_kblo[o + 1] = l2;
        }
    } else {
        int kvh = (p - 1280) >> 6;
        const float* src = g_qkv + (size_t)s * NCOLS + 2560 + kvh * 128 + 2 * j;
        __nv_bfloat16 h1, l1, h2, l2;
        split1(src[0], h1, l1);
        split1(src[1], h2, l2);
        size_t base = (size_t)kvh * DHEAD * SEQ;
        g_vthi[base + (size_t)(2 * j)     * SEQ + s] = h1;
        g_vthi[base + (size_t)(2 * j + 1) * SEQ + s] = h2;
        g_vtlo[base + (size_t)(2 * j)     * SEQ + s] = l1;
        g_vtlo[base + (size_t)(2 * j + 1) * SEQ + s] = l2;
    }
}

// ---------------- mma.sync bf16x3 GEMM (unchanged from R3) ----------------
#define BM 128
#define BN 128
#define BKT 64
#define MATB 16384
#define BUFB (4 * MATB)
#define GSMEM (2 * BUFB)
#define NSTG (KDIM / BKT)

__device__ __forceinline__ void load_stage(uint32_t smb, int s, int m0, int n0, int tid,
                                           const __nv_bfloat16* Ahi, const __nv_bfloat16* Alo,
                                           const __nv_bfloat16* Bhi, const __nv_bfloat16* Blo) {
    uint32_t bb = smb + (s & 1) * BUFB;
    int k0 = s * BKT;
    #pragma unroll
    for (int i = 0; i < 4; i++) {
        int c = tid + i * 256;
        int r = c >> 3, ch = c & 7;
        uint32_t so = bb + SWZ(r * 128 + ch * 16);
        size_t ga = (size_t)(m0 + r) * KDIM + k0 + ch * 8;
        size_t gb = (size_t)(n0 + r) * KDIM + k0 + ch * 8;
        cp16(so,            Ahi + ga);
        cp16(so + MATB,     Alo + ga);
        cp16(so + 2 * MATB, Bhi + gb);
        cp16(so + 3 * MATB, Blo + gb);
    }
}

__global__ __launch_bounds__(256, 1) void gemm_mma_x3(
    const __nv_bfloat16* __restrict__ Ahi, const __nv_bfloat16* __restrict__ Alo,
    const __nv_bfloat16* __restrict__ Bhi, const __nv_bfloat16* __restrict__ Blo,
    const float* __restrict__ bias, float* __restrict__ C, int N)
{
    extern __shared__ char sm[];
    const uint32_t smb = smem_u32(sm);
    const int tid = threadIdx.x;
    const int wid = tid >> 5, lid = tid & 31;
    const int m0 = blockIdx.x * BM, n0 = blockIdx.y * BN;
    const int wm = (wid & 1) * 64;
    const int wn = (wid >> 1) * 32;

    float acc[4][4][4];
    #pragma unroll
    for (int i = 0; i < 4; i++)
        #pragma unroll
        for (int j = 0; j < 4; j++)
            #pragma unroll
            for (int k = 0; k < 4; k++) acc[i][j][k] = 0.f;

    const int arow = lid & 15;
    const int asel = (lid >> 4) * 16;
    const int brow = ((lid >> 4) << 3) + (lid & 7);
    const int bsel = ((lid >> 3) & 1) * 16;

    load_stage(smb, 0, m0, n0, tid, Ahi, Alo, Bhi, Blo);
    CP_COMMIT();

    for (int s = 0; s < NSTG; s++) {
        if (s + 1 < NSTG) {
            load_stage(smb, s + 1, m0, n0, tid, Ahi, Alo, Bhi, Blo);
            CP_COMMIT();
            asm volatile("cp.async.wait_group 1;" ::: "memory");
        } else {
            asm volatile("cp.async.wait_group 0;" ::: "memory");
        }
        __syncthreads();

        uint32_t bb = smb + (s & 1) * BUFB;
        #pragma unroll
        for (int kk = 0; kk < 4; kk++) {
            uint32_t ah[4][4], al[4][4];
            #pragma unroll
            for (int ms = 0; ms < 4; ms++) {
                uint32_t off = SWZ((wm + ms * 16 + arow) * 128 + kk * 32 + asel);
                ldsm4(ah[ms], bb + off);
                ldsm4(al[ms], bb + MATB + off);
            }
            uint32_t bh[2][4], bl[2][4];
            #pragma unroll
            for (int ns = 0; ns < 2; ns++) {
                uint32_t off = SWZ((wn + ns * 16 + brow) * 128 + kk * 32 + bsel);
                ldsm4(bh[ns], bb + 2 * MATB + off);
                ldsm4(bl[ns], bb + 3 * MATB + off);
            }
            #pragma unroll
            for (int ms = 0; ms < 4; ms++)
                #pragma unroll
                for (int n8 = 0; n8 < 4; n8++) {
                    const uint32_t* ph = &bh[n8 >> 1][(n8 & 1) * 2];
                    const uint32_t* pl = &bl[n8 >> 1][(n8 & 1) * 2];
                    mma_bf16(acc[ms][n8], ah[ms], ph);
                    mma_bf16(acc[ms][n8], ah[ms], pl);
                    mma_bf16(acc[ms][n8], al[ms], ph);
                }
        }
        __syncthreads();
    }

    const int erow = lid >> 2, ecol = (lid & 3) * 2;
    #pragma unroll
    for (int ms = 0; ms < 4; ms++) {
        int r0 = m0 + wm + ms * 16 + erow;
        #pragma unroll
        for (int n8 = 0; n8 < 4; n8++) {
            int c = n0 + wn + n8 * 8 + ecol;
            float2 bv = *(const float2*)&bias[c];
            float2 o0 = make_float2(acc[ms][n8][0] + bv.x, acc[ms][n8][1] + bv.y);
            float2 o1 = make_float2(acc[ms][n8][2] + bv.x, acc[ms][n8][3] + bv.y);
            *(float2*)&C[(size_t)r0 * N + c]       = o0;
            *(float2*)&C[(size_t)(r0 + 8) * N + c] = o1;
        }
    }
}

// ---------------- flash attention on tensor cores (bf16x3) ----------------
// CTA: 128 q rows x 1 head. 8 warps, warp w -> q rows [w*16, w*16+16).
// smem: Q 4x[128][64] (hi0,hi1,lo0,lo1) 64KB at 0
//       K stages 2 x 4x[64][64] (hi0,hi1,lo0,lo1) 64KB at 65536
//       Vt stages 2 x 2x[128][64] (hi,lo) 64KB at 131072
#define SMQ 0
#define SMK 65536
#define SMV 131072
#define ATT_SMEM 196608

__device__ __forceinline__ void load_kv_stage(uint32_t smb, int buf, int kv0, int tid,
                                              const __nv_bfloat16* khi, const __nv_bfloat16* klo,
                                              const __nv_bfloat16* vhi, const __nv_bfloat16* vlo) {
    // K: 4 sub-blocks [64][64] = 512 chunks each
    #pragma unroll
    for (int sb = 0; sb < 4; sb++) {
        int isl = sb >> 1, b = sb & 1;
        const __nv_bfloat16* src = isl ? klo : khi;
        #pragma unroll
        for (int i = 0; i < 2; i++) {
            int c = tid + i * 256;
            int r = c >> 3, ch = c & 7;
            cp16(smb + SMK + buf * 32768 + sb * 8192 + SWZ(r * 128 + ch * 16),
                 src + (size_t)(kv0 + r) * DHEAD + b * 64 + ch * 8);
        }
    }
    // Vt: 2 blocks [128][64] = 1024 chunks each
    #pragma unroll
    for (int isl = 0; isl < 2; isl++) {
        const __nv_bfloat16* src = isl ? vlo : vhi;
        #pragma unroll
        for (int i = 0; i < 4; i++) {
            int c = tid + i * 256;
            int d = c >> 3, ch = c & 7;
            cp16(smb + SMV + buf * 32768 + isl * 16384 + SWZ(d * 128 + ch * 16),
                 src + (size_t)d * SEQ + kv0 + ch * 8);
        }
    }
}

__global__ __launch_bounds__(256, 1) void attn_mma() {
    extern __shared__ char sm[];
    const uint32_t smb = smem_u32(sm);
    const int tid = threadIdx.x;
    const int wid = tid >> 5, lid = tid & 31;
    const int qb = (int)(gridDim.x - 1) - (int)blockIdx.x;   // big blocks first
    const int h = blockIdx.y;
    const int kvh = h >> 2;
    const int q0 = qb * 128;
    const int nkv = 2 * qb + 2;
    const int w16 = wid * 16;

    const int arow = lid & 15;
    const int asel = (lid >> 4) * 16;
    const int brow = ((lid >> 4) << 3) + (lid & 7);
    const int bsel = ((lid >> 3) & 1) * 16;

    const __nv_bfloat16* khi = g_kbhi + (size_t)kvh * SEQ * DHEAD;
    const __nv_bfloat16* klo = g_kblo + (size_t)kvh * SEQ * DHEAD;
    const __nv_bfloat16* vhi = g_vthi + (size_t)kvh * DHEAD * SEQ;
    const __nv_bfloat16* vlo = g_vtlo + (size_t)kvh * DHEAD * SEQ;

    // prologue: Q tile (once) + KV stage 0
    #pragma unroll
    for (int sb = 0; sb < 4; sb++) {
        int isl = sb >> 1, b = sb & 1;
        const __nv_bfloat16* src = isl ? g_qblo : g_qbhi;
        #pragma unroll
        for (int i = 0; i < 4; i++) {
            int c = tid + i * 256;
            int r = c >> 3, ch = c & 7;
            cp16(smb + SMQ + sb * 16384 + SWZ(r * 128 + ch * 16),
                 src + (size_t)(q0 + r) * DMODEL + h * DHEAD + b * 64 + ch * 8);
        }
    }
    load_kv_stage(smb, 0, 0, tid, khi, klo, vhi, vlo);
    CP_COMMIT();

    float oacc[16][4];
    #pragma unroll
    for (int i = 0; i < 16; i++)
        #pragma unroll
        for (int j = 0; j < 4; j++) oacc[i][j] = 0.f;
    float m2[2] = {-1e30f, -1e30f};
    float l2[2] = {0.f, 0.f};
    const float KE = (float)(1.4426950408889634 / 11.313708498984761);

    for (int kb = 0; kb < nkv; kb++) {
        if (kb + 1 < nkv) {
            load_kv_stage(smb, (kb + 1) & 1, (kb + 1) * 64, tid, khi, klo, vhi, vlo);
            CP_COMMIT();
            asm volatile("cp.async.wait_group 1;" ::: "memory");
        } else {
            asm volatile("cp.async.wait_group 0;" ::: "memory");
        }
        __syncthreads();

        const uint32_t kbase = smb + SMK + (kb & 1) * 32768;
        const uint32_t vbase = smb + SMV + (kb & 1) * 32768;

        // ---- S = Q K^T (bf16x3) ----
        float sacc[8][4];
        #pragma unroll
        for (int i = 0; i < 8; i++)
            #pragma unroll
            for (int j = 0; j < 4; j++) sacc[i][j] = 0.f;

        #pragma unroll
        for (int kk = 0; kk < 8; kk++) {
            int b = kk >> 2, koff = (kk & 3) * 32;
            uint32_t ah[4], al[4];
            uint32_t qoff = smb + SMQ + b * 16384 + SWZ((w16 + arow) * 128 + koff + asel);
            ldsm4(ah, qoff);
            ldsm4(al, qoff + 32768);
            #pragma unroll
            for (int ns = 0; ns < 4; ns++) {
                uint32_t bh[4], bl[4];
                uint32_t boff = kbase + b * 8192 + SWZ((ns * 16 + brow) * 128 + koff + bsel);
                ldsm4(bh, boff);
                ldsm4(bl, boff + 16384);
                mma_bf16(sacc[2 * ns],     ah, bh);     mma_bf16(sacc[2 * ns],     ah, bl);     mma_bf16(sacc[2 * ns],     al, bh);
                mma_bf16(sacc[2 * ns + 1], ah, bh + 2); mma_bf16(sacc[2 * ns + 1], ah, bl + 2); mma_bf16(sacc[2 * ns + 1], al, bh + 2);
            }
        }

        // ---- online softmax ----
        const int kv0 = kb * 64;
        const bool dodiag = (kb >= nkv - 2);
        #pragma unroll
        for (int g = 0; g < 2; g++) {
            int grow = q0 + w16 + (lid >> 2) + g * 8;
            if (dodiag) {
                #pragma unroll
                for (int n8 = 0; n8 < 8; n8++) {
                    int col = kv0 + n8 * 8 + (lid & 3) * 2;
                    if (col > grow)     sacc[n8][2 * g]     = -1e30f;
                    if (col + 1 > grow) sacc[n8][2 * g + 1] = -1e30f;
                }
            }
            float mt = -1e30f;
            #pragma unroll
            for (int n8 = 0; n8 < 8; n8++)
                mt = fmaxf(mt, fmaxf(sacc[n8][2 * g], sacc[n8][2 * g + 1]));
            mt = fmaxf(mt, __shfl_xor_sync(0xffffffffu, mt, 1));
            mt = fmaxf(mt, __shfl_xor_sync(0xffffffffu, mt, 2));
            float mnew = fmaxf(m2[g], mt);
            float alpha = ex2f((m2[g] - mnew) * KE);
            float ls = 0.f;
            #pragma unroll
            for (int n8 = 0; n8 < 8; n8++) {
                float p0 = ex2f((sacc[n8][2 * g]     - mnew) * KE);
                float p1 = ex2f((sacc[n8][2 * g + 1] - mnew) * KE);
                sacc[n8][2 * g] = p0; sacc[n8][2 * g + 1] = p1;
                ls += p0 + p1;
            }
            ls += __shfl_xor_sync(0xffffffffu, ls, 1);
            ls += __shfl_xor_sync(0xffffffffu, ls, 2);
            l2[g] = l2[g] * alpha + ls;
            m2[g] = mnew;
            #pragma unroll
            for (int t = 0; t < 16; t++) {
                oacc[t][2 * g]     *= alpha;
                oacc[t][2 * g + 1] *= alpha;
            }
        }

        // ---- O += P V  (P frags straight from S accum regs, bf16x3) ----
        #pragma unroll
        for (int t = 0; t < 4; t++) {
            uint32_t pa[4], pl[4];
            split2(sacc[2 * t][0],     sacc[2 * t][1],     pa[0], pl[0]);
            split2(sacc[2 * t][2],     sacc[2 * t][3],     pa[1], pl[1]);
            split2(sacc[2 * t + 1][0], sacc[2 * t + 1][1], pa[2], pl[2]);
            split2(sacc[2 * t + 1][2], sacc[2 * t + 1][3], pa[3], pl[3]);
            #pragma unroll
            for (int ns = 0; ns < 8; ns++) {
                uint32_t vh[4], vl[4];
                uint32_t voff = vbase + SWZ((ns * 16 + brow) * 128 + t * 32 + bsel);
                ldsm4(vh, voff);
                ldsm4(vl, voff + 16384);
                mma_bf16(oacc[2 * ns],     pa, vh);     mma_bf16(oacc[2 * ns],     pa, vl);     mma_bf16(oacc[2 * ns],     pl, vh);
                mma_bf16(oacc[2 * ns + 1], pa, vh + 2); mma_bf16(oacc[2 * ns + 1], pa, vl + 2); mma_bf16(oacc[2 * ns + 1], pl, vh + 2);
            }
        }
        __syncthreads();
    }

    // ---- epilogue: z = O / l, write bf16 hi/lo splits directly ----
    float inv0 = 1.f / l2[0], inv1 = 1.f / l2[1];
    int r0 = q0 + w16 + (lid >> 2);
    int cb = h * DHEAD + (lid & 3) * 2;
    #pragma unroll
    for (int n8 = 0; n8 < 16; n8++) {
        int col = cb + n8 * 8;
        float z0 = oacc[n8][0] * inv0, z1 = oacc[n8][1] * inv0;
        float z2 = oacc[n8][2] * inv1, z3 = oacc[n8][3] * inv1;
        __nv_bfloat16 h0, l0, h1, l1, h2, l2b, h3, l3;
        split1(z0, h0, l0); split1(z1, h1, l1);
        split1(z2, h2, l2b); split1(z3, h3, l3);
        *(__nv_bfloat162*)&g_zhi[(size_t)r0 * DMODEL + col]       = __nv_bfloat162(h0, h1);
        *(__nv_bfloat162*)&g_zlo[(size_t)r0 * DMODEL + col]       = __nv_bfloat162(l0, l1);
        *(__nv_bfloat162*)&g_zhi[(size_t)(r0 + 8) * DMODEL + col] = __nv_bfloat162(h2, h3);
        *(__nv_bfloat162*)&g_zlo[(size_t)(r0 + 8) * DMODEL + col] = __nv_bfloat162(l2b, l3);
    }
}

// ---------------- launcher ----------------
extern "C" void kernel_launch(void* const* d_in, const int* in_sizes, int n_in,
                              void* d_out, int out_size) {
    const float* x  = (const float*)d_in[0];
    const float* WQ = (const float*)d_in[1];
    const float* WK = (const float*)d_in[2];
    const float* WV = (const float*)d_in[3];
    const float* WO = (const float*)d_in[4];
    const float* bQ = (const float*)d_in[5];
    const float* bK = (const float*)d_in[6];
    const float* bV = (const float*)d_in[7];
    const float* bO = (const float*)d_in[8];
    float* out = (float*)d_out;

    float *bcat, *qkv;
    __nv_bfloat16 *xhi, *xlo, *zhi, *zlo, *Wthi, *Wtlo, *WOthi, *WOtlo;
    cudaGetSymbolAddress((void**)&bcat,  g_bcat);
    cudaGetSymbolAddress((void**)&qkv,   g_qkv);
    cudaGetSymbolAddress((void**)&xhi,   g_xhi);
    cudaGetSymbolAddress((void**)&xlo,   g_xlo);
    cudaGetSymbolAddress((void**)&zhi,   g_zhi);
    cudaGetSymbolAddress((void**)&zlo,   g_zlo);
    cudaGetSymbolAddress((void**)&Wthi,  g_Wthi);
    cudaGetSymbolAddress((void**)&Wtlo,  g_Wtlo);
    cudaGetSymbolAddress((void**)&WOthi, g_WOthi);
    cudaGetSymbolAddress((void**)&WOtlo, g_WOtlo);

    cudaFuncSetAttribute(gemm_mma_x3, cudaFuncAttributeMaxDynamicSharedMemorySize, GSMEM);
    cudaFuncSetAttribute(attn_mma, cudaFuncAttributeMaxDynamicSharedMemorySize, ATT_SMEM);

    // 1) weight repacks + input split + rotary table
    repack_wqkv<<<(NCOLS * KDIM + 255) / 256, 256>>>(WQ, WK, WV, bQ, bK, bV);
    repack_wo<<<(DMODEL * KDIM + 255) / 256, 256>>>(WO);
    split_f32<<<(SEQ * DMODEL + 255) / 256, 256>>>(x, xhi, xlo, SEQ * DMODEL);
    rotab_kernel<<<(SEQ * 64 + 255) / 256, 256>>>();

    // 2) QKV projection on HMMA
    {
        dim3 grid(SEQ / BM, NCOLS / BN);
        gemm_mma_x3<<<grid, 256, GSMEM>>>(xhi, xlo, Wthi, Wtlo, bcat, qkv, NCOLS);
    }
    // 3) rotary + bf16 split of q/k, split+transpose of v
    {
        dim3 grid(6, SEQ);
        preconvert<<<grid, 256>>>();
    }
    // 4) causal flash attention on HMMA -> zhi/zlo
    {
        dim3 grid(SEQ / 128, NH);
        attn_mma<<<grid, 256, ATT_SMEM>>>();
    }
    // 5) O-projection on HMMA
    {
        dim3 grid(SEQ / BM, DMODEL / BN);
        gemm_mma_x3<<<grid, 256, GSMEM>>>(zhi, zlo, WOthi, WOtlo, bO, out, DMODEL);
    }
}